// round 5
// baseline (speedup 1.0000x reference)
#include <cuda_runtime.h>

#define Tn 256
#define Bn 64
#define Dn 768
#define Rn 2048
#define KS 8
#define KC (Rn / KS)   // 256 k per split

// Scratch (static __device__ arrays: allocation-guard safe)
__device__ float g_P[(size_t)Tn * Rn * Bn];   // [t][r][b] : input projection + bias
__device__ float g_x0[Rn * Bn];               // state ping [r][b]
__device__ float g_x1[Rn * Bn];               // state pong [r][b]
__device__ float g_part[KS][Rn][Bn];          // k-split partial sums, 4 MB
__device__ int   g_cnt[64];                   // per-rtile arrival counters

// ---- packed f32x2 helpers (Blackwell sm_103a) ----
__device__ __forceinline__ void ffma2(unsigned long long& d, unsigned long long a, unsigned long long b) {
    asm("fma.rn.f32x2 %0, %1, %2, %0;" : "+l"(d) : "l"(a), "l"(b));
}
__device__ __forceinline__ unsigned long long pack2(float lo, float hi) {
    unsigned long long r;
    asm("mov.b64 %0, {%1, %2};" : "=l"(r) : "f"(lo), "f"(hi));
    return r;
}
__device__ __forceinline__ void unpack2(unsigned long long v, float& lo, float& hi) {
    asm("mov.b64 {%0, %1}, %2;" : "=f"(lo), "=f"(hi) : "l"(v));
}

// accurate tanh independent of fast-math flags (~1e-6 rel)
__device__ __forceinline__ float tanh_acc(float x) {
    float ax = fabsf(x);
    float e  = __expf(-2.0f * ax);
    float r  = (1.0f - e) / (1.0f + e);
    return copysignf(r, x);
}

// ---------------------------------------------------------------------------
// init: xT[r][b] = initial_state[r]; zero counters
// ---------------------------------------------------------------------------
__global__ void init_x_kernel(const float* __restrict__ init_state) {
    int i = blockIdx.x * blockDim.x + threadIdx.x;
    if (i < Rn * Bn) g_x0[i] = init_state[i >> 6];
    if (i < 64) g_cnt[i] = 0;
}

// ---------------------------------------------------------------------------
// proj: g_P[t][r][b] = sum_d inp[t][b][d] * Win[r][d] + bias[r]
// grid (Rn/64, Tn), block 128.
// ---------------------------------------------------------------------------
__global__ __launch_bounds__(128) void proj_kernel(const float* __restrict__ inp,
                                                   const float* __restrict__ win,
                                                   const float* __restrict__ bias) {
    __shared__ __align__(16) float As[16][64];   // [k][b]
    __shared__ __align__(16) float Bs[16][64];   // [k][r]
    const int t  = blockIdx.y;
    const int rt = blockIdx.x;
    const int tid = threadIdx.x;
    const int tx = tid & 15;        // b-group
    const int ty = tid >> 4;        // r-group

    unsigned long long acc[4][4];
#pragma unroll
    for (int i = 0; i < 4; i++)
#pragma unroll
        for (int j = 0; j < 4; j++) acc[i][j] = 0ULL;

    const int lrow = tid >> 1;
    const int lcol = (tid & 1) * 8;
    const float* Ap = inp + (size_t)t * Bn * Dn + (size_t)lrow * Dn + lcol;
    const float* Bp = win + (size_t)rt * 64 * Dn + (size_t)lrow * Dn + lcol;

    for (int kk = 0; kk < Dn; kk += 16) {
        float4 a0 = *(const float4*)(Ap + kk);
        float4 a1 = *(const float4*)(Ap + kk + 4);
        float4 b0 = *(const float4*)(Bp + kk);
        float4 b1 = *(const float4*)(Bp + kk + 4);
        __syncthreads();
        As[lcol + 0][lrow] = a0.x; As[lcol + 1][lrow] = a0.y;
        As[lcol + 2][lrow] = a0.z; As[lcol + 3][lrow] = a0.w;
        As[lcol + 4][lrow] = a1.x; As[lcol + 5][lrow] = a1.y;
        As[lcol + 6][lrow] = a1.z; As[lcol + 7][lrow] = a1.w;
        Bs[lcol + 0][lrow] = b0.x; Bs[lcol + 1][lrow] = b0.y;
        Bs[lcol + 2][lrow] = b0.z; Bs[lcol + 3][lrow] = b0.w;
        Bs[lcol + 4][lrow] = b1.x; Bs[lcol + 5][lrow] = b1.y;
        Bs[lcol + 6][lrow] = b1.z; Bs[lcol + 7][lrow] = b1.w;
        __syncthreads();
#pragma unroll
        for (int k = 0; k < 16; k++) {
            float4 av = *(const float4*)&As[k][tx * 4];
            unsigned long long ad0 = pack2(av.x, av.x);
            unsigned long long ad1 = pack2(av.y, av.y);
            unsigned long long ad2 = pack2(av.z, av.z);
            unsigned long long ad3 = pack2(av.w, av.w);
            ulonglong2 w0 = *(const ulonglong2*)&Bs[k][ty * 8];
            ulonglong2 w1 = *(const ulonglong2*)&Bs[k][ty * 8 + 4];
            ffma2(acc[0][0], ad0, w0.x); ffma2(acc[0][1], ad0, w0.y);
            ffma2(acc[0][2], ad0, w1.x); ffma2(acc[0][3], ad0, w1.y);
            ffma2(acc[1][0], ad1, w0.x); ffma2(acc[1][1], ad1, w0.y);
            ffma2(acc[1][2], ad1, w1.x); ffma2(acc[1][3], ad1, w1.y);
            ffma2(acc[2][0], ad2, w0.x); ffma2(acc[2][1], ad2, w0.y);
            ffma2(acc[2][2], ad2, w1.x); ffma2(acc[2][3], ad2, w1.y);
            ffma2(acc[3][0], ad3, w0.x); ffma2(acc[3][1], ad3, w0.y);
            ffma2(acc[3][2], ad3, w1.x); ffma2(acc[3][3], ad3, w1.y);
        }
    }

    float c[4][8];
#pragma unroll
    for (int bb = 0; bb < 4; bb++)
#pragma unroll
        for (int rp = 0; rp < 4; rp++) {
            float lo, hi;
            unpack2(acc[bb][rp], lo, hi);
            c[bb][rp * 2] = lo;
            c[bb][rp * 2 + 1] = hi;
        }
#pragma unroll
    for (int j = 0; j < 8; j++) {
        int r = rt * 64 + ty * 8 + j;
        float bv = bias[r];
        float4 o = make_float4(c[0][j] + bv, c[1][j] + bv, c[2][j] + bv, c[3][j] + bv);
        *(float4*)&g_P[((size_t)t * Rn + r) * Bn + tx * 4] = o;
    }
}

// ---------------------------------------------------------------------------
// fused step: partial GEMM + last-block reduce/epilogue.
// grid (64 r-tiles of 32, 8 k-slices) = 512 CTAs, block 128.
// Inner loop per k: 1 LDS.128 (x quad, used directly as 2 f32x2 operands)
//                 + 2 LDS.128 (duplicated W) + 8 ffma2  -> 73% fma mix.
// Last CTA per r-tile (atomic counter) performs the deterministic reduce:
// sum 8 partials (fixed order) + P, tanh, leak, mask, write state + out.
// ---------------------------------------------------------------------------
__global__ __launch_bounds__(128) void step_fused_kernel(const float* __restrict__ wres,
                                                         const int* __restrict__ lengths,
                                                         float* __restrict__ out,
                                                         int t) {
    __shared__ __align__(16) float Xs[32][64];   // [k][b]
    __shared__ __align__(16) float Wd[32][64];   // [k][2*rr] duplicated weights
    __shared__ int s_last;
    const int rt  = blockIdx.x;    // 0..63
    const int ks  = blockIdx.y;    // 0..7
    const int tid = threadIdx.x;
    const int bg  = tid & 15;      // b = bg*4 + bb
    const int rg  = tid >> 4;      // r = rt*32 + rg*4 + j

    const float* xsrc = (t & 1) ? g_x1 : g_x0;
    float*       xdst = (t & 1) ? g_x0 : g_x1;
    const int r0 = rt * 32;
    const int k0base = ks * KC;

    unsigned long long acc[4][2];   // [r j][b-pair]
#pragma unroll
    for (int i = 0; i < 4; i++) { acc[i][0] = 0ULL; acc[i][1] = 0ULL; }

    const int lr = tid >> 2;            // 0..31 : W row within tile
    const int lk = (tid & 3) * 8;       // 0,8,16,24 : k offset
    const float* wp = wres + (size_t)(r0 + lr) * Rn + k0base + lk;

    for (int kc = 0; kc < KC; kc += 32) {
        const float* xg = xsrc + (size_t)(k0base + kc) * Bn;
        float4 xv0 = ((const float4*)xg)[tid];
        float4 xv1 = ((const float4*)xg)[tid + 128];
        float4 xv2 = ((const float4*)xg)[tid + 256];
        float4 xv3 = ((const float4*)xg)[tid + 384];
        float4 w0 = *(const float4*)(wp + kc);
        float4 w1 = *(const float4*)(wp + kc + 4);
        __syncthreads();
        ((float4*)Xs)[tid]       = xv0;
        ((float4*)Xs)[tid + 128] = xv1;
        ((float4*)Xs)[tid + 256] = xv2;
        ((float4*)Xs)[tid + 384] = xv3;
        Wd[lk + 0][2 * lr] = w0.x; Wd[lk + 0][2 * lr + 1] = w0.x;
        Wd[lk + 1][2 * lr] = w0.y; Wd[lk + 1][2 * lr + 1] = w0.y;
        Wd[lk + 2][2 * lr] = w0.z; Wd[lk + 2][2 * lr + 1] = w0.z;
        Wd[lk + 3][2 * lr] = w0.w; Wd[lk + 3][2 * lr + 1] = w0.w;
        Wd[lk + 4][2 * lr] = w1.x; Wd[lk + 4][2 * lr + 1] = w1.x;
        Wd[lk + 5][2 * lr] = w1.y; Wd[lk + 5][2 * lr + 1] = w1.y;
        Wd[lk + 6][2 * lr] = w1.z; Wd[lk + 6][2 * lr + 1] = w1.z;
        Wd[lk + 7][2 * lr] = w1.w; Wd[lk + 7][2 * lr + 1] = w1.w;
        __syncthreads();
#pragma unroll
        for (int k = 0; k < 32; k++) {
            ulonglong2 xp  = *(const ulonglong2*)&Xs[k][bg * 4];        // (b0,b1),(b2,b3)
            ulonglong2 w01 = *(const ulonglong2*)&Wd[k][rg * 8];        // (wj0,wj0),(wj1,wj1)
            ulonglong2 w23 = *(const ulonglong2*)&Wd[k][rg * 8 + 4];    // (wj2,wj2),(wj3,wj3)
            ffma2(acc[0][0], xp.x, w01.x); ffma2(acc[0][1], xp.y, w01.x);
            ffma2(acc[1][0], xp.x, w01.y); ffma2(acc[1][1], xp.y, w01.y);
            ffma2(acc[2][0], xp.x, w23.x); ffma2(acc[2][1], xp.y, w23.x);
            ffma2(acc[3][0], xp.x, w23.y); ffma2(acc[3][1], xp.y, w23.y);
        }
    }

    // write partials
#pragma unroll
    for (int j = 0; j < 4; j++) {
        float4 o;
        unpack2(acc[j][0], o.x, o.y);
        unpack2(acc[j][1], o.z, o.w);
        *(float4*)&g_part[ks][r0 + rg * 4 + j][bg * 4] = o;
    }

    // last-block reduce for this r-tile
    __threadfence();
    __syncthreads();
    if (tid == 0) {
        int old = atomicAdd(&g_cnt[rt], 1);
        s_last = ((old & (KS - 1)) == (KS - 1)) ? 1 : 0;
    }
    __syncthreads();
    if (s_last) {
        __threadfence();
        const float* P_t = g_P + (size_t)t * Rn * Bn;
#pragma unroll
        for (int i = 0; i < 16; i++) {
            int idx = i * 128 + tid;            // 0..2047, b fast
            int rr  = idx >> 6;
            int b   = idx & 63;
            int r   = r0 + rr;
            float s = P_t[(size_t)r * Bn + b];
#pragma unroll
            for (int k2 = 0; k2 < KS; k2++) s += g_part[k2][r][b];
            float xold = xsrc[(size_t)r * Bn + b];
            float m    = (lengths[b] > t) ? 0.5f : 0.0f;   // mask * lr (lr = 1-lr = 0.5)
            float xn   = m * (xold + tanh_acc(s));
            xdst[(size_t)r * Bn + b] = xn;
            out[((size_t)b * Tn + t) * Rn + r] = xn;
        }
    }
}

// ---------------------------------------------------------------------------
// launch: init + proj + 256 fused step kernels — all graph-capturable
// ---------------------------------------------------------------------------
extern "C" void kernel_launch(void* const* d_in, const int* in_sizes, int n_in,
                              void* d_out, int out_size) {
    const float* inp     = (const float*)d_in[0];  // [T,B,D]
    const int*   lengths = (const int*)d_in[1];    // [B]
    const float* win     = (const float*)d_in[2];  // [R,D]
    const float* wres    = (const float*)d_in[3];  // [R,R]
    const float* bias    = (const float*)d_in[4];  // [R]
    const float* x0in    = (const float*)d_in[5];  // [R]
    float* out = (float*)d_out;                    // [B,T,R]

    init_x_kernel<<<(Rn * Bn + 255) / 256, 256>>>(x0in);
    proj_kernel<<<dim3(Rn / 64, Tn), 128>>>(inp, win, bias);
    for (int t = 0; t < Tn; t++) {
        step_fused_kernel<<<dim3(64, KS), 128>>>(wres, lengths, out, t);
    }
}

// round 6
// speedup vs baseline: 1.3567x; 1.3567x over previous
#include <cuda_runtime.h>

#define Tn 256
#define Bn 64
#define Dn 768
#define Rn 2048
#define KS 8
#define KC (Rn / KS)   // 256 k per split

// Scratch (static __device__ arrays: allocation-guard safe)
__device__ float g_P[(size_t)Tn * Rn * Bn];   // [t][r][b] : input projection + bias
__device__ float g_x0[Rn * Bn];               // state ping [r][b]
__device__ float g_x1[Rn * Bn];               // state pong [r][b]
__device__ float g_part[KS][Rn][Bn];          // k-split partial sums, 4 MB

// ---- packed f32x2 helpers (Blackwell sm_103a) ----
__device__ __forceinline__ void ffma2(unsigned long long& d, unsigned long long a, unsigned long long b) {
    asm("fma.rn.f32x2 %0, %1, %2, %0;" : "+l"(d) : "l"(a), "l"(b));
}
__device__ __forceinline__ unsigned long long pack2(float lo, float hi) {
    unsigned long long r;
    asm("mov.b64 %0, {%1, %2};" : "=l"(r) : "f"(lo), "f"(hi));
    return r;
}
__device__ __forceinline__ void unpack2(unsigned long long v, float& lo, float& hi) {
    asm("mov.b64 {%0, %1}, %2;" : "=f"(lo), "=f"(hi) : "l"(v));
}

// accurate tanh independent of fast-math flags (~1e-6 rel)
__device__ __forceinline__ float tanh_acc(float x) {
    float ax = fabsf(x);
    float e  = __expf(-2.0f * ax);
    float r  = (1.0f - e) / (1.0f + e);
    return copysignf(r, x);
}

// ---------------------------------------------------------------------------
// init: xT[r][b] = initial_state[r]
// ---------------------------------------------------------------------------
__global__ void init_x_kernel(const float* __restrict__ init_state) {
    int i = blockIdx.x * blockDim.x + threadIdx.x;
    if (i < Rn * Bn) g_x0[i] = init_state[i >> 6];
}

// ---------------------------------------------------------------------------
// proj: g_P[t][r][b] = sum_d inp[t][b][d] * Win[r][d] + bias[r]
// grid (Rn/64, Tn), block 128.
// ---------------------------------------------------------------------------
__global__ __launch_bounds__(128) void proj_kernel(const float* __restrict__ inp,
                                                   const float* __restrict__ win,
                                                   const float* __restrict__ bias) {
    __shared__ __align__(16) float As[16][64];   // [k][b]
    __shared__ __align__(16) float Bs[16][64];   // [k][r]
    const int t  = blockIdx.y;
    const int rt = blockIdx.x;
    const int tid = threadIdx.x;
    const int tx = tid & 15;        // b-group
    const int ty = tid >> 4;        // r-group

    unsigned long long acc[4][4];
#pragma unroll
    for (int i = 0; i < 4; i++)
#pragma unroll
        for (int j = 0; j < 4; j++) acc[i][j] = 0ULL;

    const int lrow = tid >> 1;
    const int lcol = (tid & 1) * 8;
    const float* Ap = inp + (size_t)t * Bn * Dn + (size_t)lrow * Dn + lcol;
    const float* Bp = win + (size_t)rt * 64 * Dn + (size_t)lrow * Dn + lcol;

    for (int kk = 0; kk < Dn; kk += 16) {
        float4 a0 = *(const float4*)(Ap + kk);
        float4 a1 = *(const float4*)(Ap + kk + 4);
        float4 b0 = *(const float4*)(Bp + kk);
        float4 b1 = *(const float4*)(Bp + kk + 4);
        __syncthreads();
        As[lcol + 0][lrow] = a0.x; As[lcol + 1][lrow] = a0.y;
        As[lcol + 2][lrow] = a0.z; As[lcol + 3][lrow] = a0.w;
        As[lcol + 4][lrow] = a1.x; As[lcol + 5][lrow] = a1.y;
        As[lcol + 6][lrow] = a1.z; As[lcol + 7][lrow] = a1.w;
        Bs[lcol + 0][lrow] = b0.x; Bs[lcol + 1][lrow] = b0.y;
        Bs[lcol + 2][lrow] = b0.z; Bs[lcol + 3][lrow] = b0.w;
        Bs[lcol + 4][lrow] = b1.x; Bs[lcol + 5][lrow] = b1.y;
        Bs[lcol + 6][lrow] = b1.z; Bs[lcol + 7][lrow] = b1.w;
        __syncthreads();
#pragma unroll
        for (int k = 0; k < 16; k++) {
            float4 av = *(const float4*)&As[k][tx * 4];
            unsigned long long ad0 = pack2(av.x, av.x);
            unsigned long long ad1 = pack2(av.y, av.y);
            unsigned long long ad2 = pack2(av.z, av.z);
            unsigned long long ad3 = pack2(av.w, av.w);
            ulonglong2 w0 = *(const ulonglong2*)&Bs[k][ty * 8];
            ulonglong2 w1 = *(const ulonglong2*)&Bs[k][ty * 8 + 4];
            ffma2(acc[0][0], ad0, w0.x); ffma2(acc[0][1], ad0, w0.y);
            ffma2(acc[0][2], ad0, w1.x); ffma2(acc[0][3], ad0, w1.y);
            ffma2(acc[1][0], ad1, w0.x); ffma2(acc[1][1], ad1, w0.y);
            ffma2(acc[1][2], ad1, w1.x); ffma2(acc[1][3], ad1, w1.y);
            ffma2(acc[2][0], ad2, w0.x); ffma2(acc[2][1], ad2, w0.y);
            ffma2(acc[2][2], ad2, w1.x); ffma2(acc[2][3], ad2, w1.y);
            ffma2(acc[3][0], ad3, w0.x); ffma2(acc[3][1], ad3, w0.y);
            ffma2(acc[3][2], ad3, w1.x); ffma2(acc[3][3], ad3, w1.y);
        }
    }

    float c[4][8];
#pragma unroll
    for (int bb = 0; bb < 4; bb++)
#pragma unroll
        for (int rp = 0; rp < 4; rp++) {
            float lo, hi;
            unpack2(acc[bb][rp], lo, hi);
            c[bb][rp * 2] = lo;
            c[bb][rp * 2 + 1] = hi;
        }
#pragma unroll
    for (int j = 0; j < 8; j++) {
        int r = rt * 64 + ty * 8 + j;
        float bv = bias[r];
        float4 o = make_float4(c[0][j] + bv, c[1][j] + bv, c[2][j] + bv, c[3][j] + bv);
        *(float4*)&g_P[((size_t)t * Rn + r) * Bn + tx * 4] = o;
    }
}

// ---------------------------------------------------------------------------
// recurrence partial: g_part[ks][r][b] = sum_{k in slice ks} Wres[r][k]*xT[k][b]
// grid (64 r-tiles of 32, 8 k-slices) = 512 CTAs, block 128.
// Inner loop per k: 1 LDS.128 (x quad = 2 f32x2 operands, used directly)
//                 + 2 LDS.128 (duplicated W) + 8 ffma2  -> 11 instr / 16 MACs.
// No fences, no atomics — the graph-node boundary orders the reduce.
// ---------------------------------------------------------------------------
__global__ __launch_bounds__(128) void part_kernel(const float* __restrict__ wres, int t) {
    __shared__ __align__(16) float Xs[32][64];   // [k][b]
    __shared__ __align__(16) float Wd[32][64];   // [k][2*rr] duplicated weights
    const int rt  = blockIdx.x;    // 0..63
    const int ks  = blockIdx.y;    // 0..7
    const int tid = threadIdx.x;
    const int bg  = tid & 15;      // b = bg*4 + bb
    const int rg  = tid >> 4;      // r = rt*32 + rg*4 + j

    const float* xsrc = (t & 1) ? g_x1 : g_x0;
    const int r0 = rt * 32;
    const int k0base = ks * KC;

    unsigned long long acc[4][2];   // [r j][b-pair]
#pragma unroll
    for (int i = 0; i < 4; i++) { acc[i][0] = 0ULL; acc[i][1] = 0ULL; }

    const int lr = tid >> 2;            // 0..31 : W row within tile
    const int lk = (tid & 3) * 8;       // 0,8,16,24 : k offset
    const float* wp = wres + (size_t)(r0 + lr) * Rn + k0base + lk;

    for (int kc = 0; kc < KC; kc += 32) {
        const float* xg = xsrc + (size_t)(k0base + kc) * Bn;
        float4 xv0 = ((const float4*)xg)[tid];
        float4 xv1 = ((const float4*)xg)[tid + 128];
        float4 xv2 = ((const float4*)xg)[tid + 256];
        float4 xv3 = ((const float4*)xg)[tid + 384];
        float4 w0 = *(const float4*)(wp + kc);
        float4 w1 = *(const float4*)(wp + kc + 4);
        __syncthreads();
        ((float4*)Xs)[tid]       = xv0;
        ((float4*)Xs)[tid + 128] = xv1;
        ((float4*)Xs)[tid + 256] = xv2;
        ((float4*)Xs)[tid + 384] = xv3;
        Wd[lk + 0][2 * lr] = w0.x; Wd[lk + 0][2 * lr + 1] = w0.x;
        Wd[lk + 1][2 * lr] = w0.y; Wd[lk + 1][2 * lr + 1] = w0.y;
        Wd[lk + 2][2 * lr] = w0.z; Wd[lk + 2][2 * lr + 1] = w0.z;
        Wd[lk + 3][2 * lr] = w0.w; Wd[lk + 3][2 * lr + 1] = w0.w;
        Wd[lk + 4][2 * lr] = w1.x; Wd[lk + 4][2 * lr + 1] = w1.x;
        Wd[lk + 5][2 * lr] = w1.y; Wd[lk + 5][2 * lr + 1] = w1.y;
        Wd[lk + 6][2 * lr] = w1.z; Wd[lk + 6][2 * lr + 1] = w1.z;
        Wd[lk + 7][2 * lr] = w1.w; Wd[lk + 7][2 * lr + 1] = w1.w;
        __syncthreads();
#pragma unroll
        for (int k = 0; k < 32; k++) {
            ulonglong2 xp  = *(const ulonglong2*)&Xs[k][bg * 4];        // (b0,b1),(b2,b3)
            ulonglong2 w01 = *(const ulonglong2*)&Wd[k][rg * 8];        // (wj0,wj0),(wj1,wj1)
            ulonglong2 w23 = *(const ulonglong2*)&Wd[k][rg * 8 + 4];    // (wj2,wj2),(wj3,wj3)
            ffma2(acc[0][0], xp.x, w01.x); ffma2(acc[0][1], xp.y, w01.x);
            ffma2(acc[1][0], xp.x, w01.y); ffma2(acc[1][1], xp.y, w01.y);
            ffma2(acc[2][0], xp.x, w23.x); ffma2(acc[2][1], xp.y, w23.x);
            ffma2(acc[3][0], xp.x, w23.y); ffma2(acc[3][1], xp.y, w23.y);
        }
    }

#pragma unroll
    for (int j = 0; j < 4; j++) {
        float4 o;
        unpack2(acc[j][0], o.x, o.y);
        unpack2(acc[j][1], o.z, o.w);
        *(float4*)&g_part[ks][r0 + rg * 4 + j][bg * 4] = o;
    }
}

// ---------------------------------------------------------------------------
// reduce + epilogue: sum KS partials + P, tanh, leak, mask, write state + out.
// grid 256, block 256 — each thread handles one (r-pair, b): ~20 independent
// loads in flight, 2x the thread parallelism of R4 (was latency-bound).
// Fixed summation order -> deterministic.
// ---------------------------------------------------------------------------
__global__ __launch_bounds__(256) void reduce_kernel(const int* __restrict__ lengths,
                                                     float* __restrict__ out,
                                                     int t) {
    const int idx = blockIdx.x * 256 + threadIdx.x;   // 0..65535
    const int b   = idx & 63;
    const int rp  = idx >> 6;                          // 0..1023
    const int r0  = rp * 2;

    const float* xsrc = (t & 1) ? g_x1 : g_x0;
    float*       xdst = (t & 1) ? g_x0 : g_x1;
    const float* P_t  = g_P + (size_t)t * Rn * Bn;

    const float m = (lengths[b] > t) ? 0.5f : 0.0f;   // mask * lr (lr = 1-lr = 0.5)

    float2 ov;
#pragma unroll
    for (int j = 0; j < 2; j++) {
        const int r = r0 + j;
        float s = P_t[(size_t)r * Bn + b];
#pragma unroll
        for (int ksi = 0; ksi < KS; ksi++) s += g_part[ksi][r][b];
        float xold = xsrc[(size_t)r * Bn + b];
        float xn   = m * (xold + tanh_acc(s));
        xdst[(size_t)r * Bn + b] = xn;
        ((float*)&ov)[j] = xn;
    }
    *(float2*)&out[((size_t)b * Tn + t) * Rn + r0] = ov;
}

// ---------------------------------------------------------------------------
// launch: init + proj + 256 x (part, reduce) — all graph-capturable
// ---------------------------------------------------------------------------
extern "C" void kernel_launch(void* const* d_in, const int* in_sizes, int n_in,
                              void* d_out, int out_size) {
    const float* inp     = (const float*)d_in[0];  // [T,B,D]
    const int*   lengths = (const int*)d_in[1];    // [B]
    const float* win     = (const float*)d_in[2];  // [R,D]
    const float* wres    = (const float*)d_in[3];  // [R,R]
    const float* bias    = (const float*)d_in[4];  // [R]
    const float* x0in    = (const float*)d_in[5];  // [R]
    float* out = (float*)d_out;                    // [B,T,R]

    init_x_kernel<<<(Rn * Bn + 255) / 256, 256>>>(x0in);
    proj_kernel<<<dim3(Rn / 64, Tn), 128>>>(inp, win, bias);
    for (int t = 0; t < Tn; t++) {
        part_kernel<<<dim3(64, KS), 128>>>(wres, t);
        reduce_kernel<<<256, 256>>>(lengths, out, t);
    }
}

// round 8
// speedup vs baseline: 1.7667x; 1.3022x over previous
#include <cuda_runtime.h>
#include <cstdint>

#define Tn 256
#define Bn 64
#define Dn 768
#define Rn 2048
#define KS 8
#define KC (Rn / KS)   // 256 k per split

// Scratch (static __device__ arrays: allocation-guard safe)
__device__ float g_P[(size_t)Tn * Rn * Bn];   // [t][r][b] : input projection + bias
__device__ float g_x0[Rn * Bn];               // state ping [r][b]
__device__ float g_x1[Rn * Bn];               // state pong [r][b]

// ---- packed f32x2 helpers (Blackwell sm_103a) ----
__device__ __forceinline__ void ffma2(unsigned long long& d, unsigned long long a, unsigned long long b) {
    asm("fma.rn.f32x2 %0, %1, %2, %0;" : "+l"(d) : "l"(a), "l"(b));
}
__device__ __forceinline__ unsigned long long pack2(float lo, float hi) {
    unsigned long long r;
    asm("mov.b64 %0, {%1, %2};" : "=l"(r) : "f"(lo), "f"(hi));
    return r;
}
__device__ __forceinline__ void unpack2(unsigned long long v, float& lo, float& hi) {
    asm("mov.b64 {%0, %1}, %2;" : "=f"(lo), "=f"(hi) : "l"(v));
}

// ---- cluster / DSMEM helpers ----
__device__ __forceinline__ uint32_t smem_u32(const void* p) {
    uint32_t a;
    asm("{ .reg .u64 t; cvta.to.shared.u64 t, %1; cvt.u32.u64 %0, t; }" : "=r"(a) : "l"(p));
    return a;
}
__device__ __forceinline__ uint32_t mapa_cluster(uint32_t local_addr, uint32_t rank) {
    uint32_t r;
    asm("mapa.shared::cluster.u32 %0, %1, %2;" : "=r"(r) : "r"(local_addr), "r"(rank));
    return r;
}
__device__ __forceinline__ float ld_dsmem_f32(uint32_t addr) {
    float v;
    asm volatile("ld.shared::cluster.f32 %0, [%1];" : "=f"(v) : "r"(addr));
    return v;
}
#define CLUSTER_ARRIVE() asm volatile("barrier.cluster.arrive.aligned;" ::: "memory")
#define CLUSTER_WAIT()   asm volatile("barrier.cluster.wait.aligned;" ::: "memory")

// accurate tanh independent of fast-math flags (~1e-6 rel)
__device__ __forceinline__ float tanh_acc(float x) {
    float ax = fabsf(x);
    float e  = __expf(-2.0f * ax);
    float r  = (1.0f - e) / (1.0f + e);
    return copysignf(r, x);
}

// ---------------------------------------------------------------------------
// init: xT[r][b] = initial_state[r]
// ---------------------------------------------------------------------------
__global__ void init_x_kernel(const float* __restrict__ init_state) {
    int i = blockIdx.x * blockDim.x + threadIdx.x;
    if (i < Rn * Bn) g_x0[i] = init_state[i >> 6];
}

// ---------------------------------------------------------------------------
// proj: g_P[t][r][b] = sum_d inp[t][b][d] * Win[r][d] + bias[r]
// grid (Rn/64, Tn), block 128.  (unchanged — passing, ~0.9 ms)
// ---------------------------------------------------------------------------
__global__ __launch_bounds__(128) void proj_kernel(const float* __restrict__ inp,
                                                   const float* __restrict__ win,
                                                   const float* __restrict__ bias) {
    __shared__ __align__(16) float As[16][64];   // [k][b]
    __shared__ __align__(16) float Bs[16][64];   // [k][r]
    const int t  = blockIdx.y;
    const int rt = blockIdx.x;
    const int tid = threadIdx.x;
    const int tx = tid & 15;        // b-group
    const int ty = tid >> 4;        // r-group

    unsigned long long acc[4][4];
#pragma unroll
    for (int i = 0; i < 4; i++)
#pragma unroll
        for (int j = 0; j < 4; j++) acc[i][j] = 0ULL;

    const int lrow = tid >> 1;
    const int lcol = (tid & 1) * 8;
    const float* Ap = inp + (size_t)t * Bn * Dn + (size_t)lrow * Dn + lcol;
    const float* Bp = win + (size_t)rt * 64 * Dn + (size_t)lrow * Dn + lcol;

    for (int kk = 0; kk < Dn; kk += 16) {
        float4 a0 = *(const float4*)(Ap + kk);
        float4 a1 = *(const float4*)(Ap + kk + 4);
        float4 b0 = *(const float4*)(Bp + kk);
        float4 b1 = *(const float4*)(Bp + kk + 4);
        __syncthreads();
        As[lcol + 0][lrow] = a0.x; As[lcol + 1][lrow] = a0.y;
        As[lcol + 2][lrow] = a0.z; As[lcol + 3][lrow] = a0.w;
        As[lcol + 4][lrow] = a1.x; As[lcol + 5][lrow] = a1.y;
        As[lcol + 6][lrow] = a1.z; As[lcol + 7][lrow] = a1.w;
        Bs[lcol + 0][lrow] = b0.x; Bs[lcol + 1][lrow] = b0.y;
        Bs[lcol + 2][lrow] = b0.z; Bs[lcol + 3][lrow] = b0.w;
        Bs[lcol + 4][lrow] = b1.x; Bs[lcol + 5][lrow] = b1.y;
        Bs[lcol + 6][lrow] = b1.z; Bs[lcol + 7][lrow] = b1.w;
        __syncthreads();
#pragma unroll
        for (int k = 0; k < 16; k++) {
            float4 av = *(const float4*)&As[k][tx * 4];
            unsigned long long ad0 = pack2(av.x, av.x);
            unsigned long long ad1 = pack2(av.y, av.y);
            unsigned long long ad2 = pack2(av.z, av.z);
            unsigned long long ad3 = pack2(av.w, av.w);
            ulonglong2 w0 = *(const ulonglong2*)&Bs[k][ty * 8];
            ulonglong2 w1 = *(const ulonglong2*)&Bs[k][ty * 8 + 4];
            ffma2(acc[0][0], ad0, w0.x); ffma2(acc[0][1], ad0, w0.y);
            ffma2(acc[0][2], ad0, w1.x); ffma2(acc[0][3], ad0, w1.y);
            ffma2(acc[1][0], ad1, w0.x); ffma2(acc[1][1], ad1, w0.y);
            ffma2(acc[1][2], ad1, w1.x); ffma2(acc[1][3], ad1, w1.y);
            ffma2(acc[2][0], ad2, w0.x); ffma2(acc[2][1], ad2, w0.y);
            ffma2(acc[2][2], ad2, w1.x); ffma2(acc[2][3], ad2, w1.y);
            ffma2(acc[3][0], ad3, w0.x); ffma2(acc[3][1], ad3, w0.y);
            ffma2(acc[3][2], ad3, w1.x); ffma2(acc[3][3], ad3, w1.y);
        }
    }

    float c[4][8];
#pragma unroll
    for (int bb = 0; bb < 4; bb++)
#pragma unroll
        for (int rp = 0; rp < 4; rp++) {
            float lo, hi;
            unpack2(acc[bb][rp], lo, hi);
            c[bb][rp * 2] = lo;
            c[bb][rp * 2 + 1] = hi;
        }
#pragma unroll
    for (int j = 0; j < 8; j++) {
        int r = rt * 64 + ty * 8 + j;
        float bv = bias[r];
        float4 o = make_float4(c[0][j] + bv, c[1][j] + bv, c[2][j] + bv, c[3][j] + bv);
        *(float4*)&g_P[((size_t)t * Rn + r) * Bn + tx * 4] = o;
    }
}

// ---------------------------------------------------------------------------
// fused recurrence step via 8-CTA cluster (one cluster per 32-row r-tile).
// grid (KS=8, 64), cluster (8,1,1), block 128.
// Each CTA (rank = k-slice) computes partial[32r][64b] over its 256-k slice,
// stores it in ITS OWN SMEM, then:
//   arrive#1 (release partials) -> hide P/xold/lengths loads -> wait#1
//   -> pull 16 peer values via DSMEM into registers
//   -> arrive#2 (done reading peers) -> sum (fixed order, deterministic),
//      tanh/leak/mask, global stores -> wait#2 -> exit.
// The trailing barrier fixes the R7 crash (CTA exit while peers read DSMEM).
// ---------------------------------------------------------------------------
__global__ __launch_bounds__(128) __cluster_dims__(KS, 1, 1)
void step_cluster_kernel(const float* __restrict__ wres,
                         const int* __restrict__ lengths,
                         float* __restrict__ out,
                         int t) {
    __shared__ __align__(16) float Xs[32 * 64];   // [k][b]; reused as partial [32r][64b]
    __shared__ __align__(16) float Ws[32 * 32];   // [k][r]
    const int ks  = blockIdx.x;    // cluster rank = k-slice
    const int rt  = blockIdx.y;    // 0..63
    const int tid = threadIdx.x;
    const int bg  = tid & 15;      // b = bg*4 + bb
    const int rg  = tid >> 4;      // r = rt*32 + rg*4 + j

    const float* xsrc = (t & 1) ? g_x1 : g_x0;
    float*       xdst = (t & 1) ? g_x0 : g_x1;
    const int r0 = rt * 32;
    const int k0 = ks * KC;

    unsigned long long acc[4][2];   // [bb][r-pair]
#pragma unroll
    for (int i = 0; i < 4; i++) { acc[i][0] = 0ULL; acc[i][1] = 0ULL; }

    const int lr = tid >> 2;            // 0..31 : W row within tile
    const int lk = (tid & 3) * 8;       // 0,8,16,24 : k offset
    const float* wp = wres + (size_t)(r0 + lr) * Rn + k0 + lk;

    // prefetch chunk 0
    float4 xa, xb, xc, xd, wa, wb;
    {
        const float4* xg = (const float4*)(xsrc + (size_t)k0 * Bn);
        xa = xg[tid]; xb = xg[tid + 128]; xc = xg[tid + 256]; xd = xg[tid + 384];
        wa = *(const float4*)(wp);
        wb = *(const float4*)(wp + 4);
    }

    for (int kc = 0; kc < KC; kc += 32) {
        __syncthreads();
        ((float4*)Xs)[tid]       = xa;
        ((float4*)Xs)[tid + 128] = xb;
        ((float4*)Xs)[tid + 256] = xc;
        ((float4*)Xs)[tid + 384] = xd;
        Ws[(lk + 0) * 32 + lr] = wa.x;
        Ws[(lk + 1) * 32 + lr] = wa.y;
        Ws[(lk + 2) * 32 + lr] = wa.z;
        Ws[(lk + 3) * 32 + lr] = wa.w;
        Ws[(lk + 4) * 32 + lr] = wb.x;
        Ws[(lk + 5) * 32 + lr] = wb.y;
        Ws[(lk + 6) * 32 + lr] = wb.z;
        Ws[(lk + 7) * 32 + lr] = wb.w;
        __syncthreads();
        if (kc + 32 < KC) {   // prefetch next chunk while computing
            const float4* xg = (const float4*)(xsrc + (size_t)(k0 + kc + 32) * Bn);
            xa = xg[tid]; xb = xg[tid + 128]; xc = xg[tid + 256]; xd = xg[tid + 384];
            wa = *(const float4*)(wp + kc + 32);
            wb = *(const float4*)(wp + kc + 36);
        }
#pragma unroll
        for (int k = 0; k < 32; k++) {
            float4 xq = *(const float4*)&Xs[k * 64 + bg * 4];
            unsigned long long a0 = pack2(xq.x, xq.x);
            unsigned long long a1 = pack2(xq.y, xq.y);
            unsigned long long a2 = pack2(xq.z, xq.z);
            unsigned long long a3 = pack2(xq.w, xq.w);
            ulonglong2 w = *(const ulonglong2*)&Ws[k * 32 + rg * 4];
            ffma2(acc[0][0], a0, w.x); ffma2(acc[0][1], a0, w.y);
            ffma2(acc[1][0], a1, w.x); ffma2(acc[1][1], a1, w.y);
            ffma2(acc[2][0], a2, w.x); ffma2(acc[2][1], a2, w.y);
            ffma2(acc[3][0], a3, w.x); ffma2(acc[3][1], a3, w.y);
        }
    }

    // s[bb][j] = partial for (b = bg*4+bb, r = r0+rg*4+j)
    float s[4][4];
#pragma unroll
    for (int bb = 0; bb < 4; bb++) {
        unpack2(acc[bb][0], s[bb][0], s[bb][1]);
        unpack2(acc[bb][1], s[bb][2], s[bb][3]);
    }

    // store partial tile [32r][64b] into own SMEM (reusing Xs)
    __syncthreads();   // all Xs reads done before overwrite
#pragma unroll
    for (int j = 0; j < 4; j++) {
        float4 o = make_float4(s[0][j], s[1][j], s[2][j], s[3][j]);
        *(float4*)&Xs[(rg * 4 + j) * 64 + bg * 4] = o;
    }
    __syncthreads();   // partial complete before cluster arrive (release)
    CLUSTER_ARRIVE();  // barrier #1 arrive: my partial is published

    // hide global loads for the tail behind cluster arrival skew.
    // This CTA reduces rows [r0 + ks*4, r0 + ks*4 + 4): 256 values, 2/thread.
    int   bI[2], rlocI[2], rI[2];
    float pv[2], xo[2];
    int   lenv[2];
#pragma unroll
    for (int i = 0; i < 2; i++) {
        int v    = tid + i * 128;       // 0..255
        bI[i]    = v & 63;
        rlocI[i] = ks * 4 + (v >> 6);   // row within 32-row tile
        rI[i]    = r0 + rlocI[i];
        pv[i]   = g_P[((size_t)t * Rn + rI[i]) * Bn + bI[i]];
        xo[i]   = xsrc[(size_t)rI[i] * Bn + bI[i]];
        lenv[i] = lengths[bI[i]];
    }

    CLUSTER_WAIT();    // barrier #1 wait: all partials visible

    // pull all peer partials into registers (16 DSMEM loads, MLP-overlapped)
    const uint32_t base = smem_u32(Xs);
    float pr[2][KS];
#pragma unroll
    for (int i = 0; i < 2; i++) {
        const uint32_t off = base + (uint32_t)(rlocI[i] * 64 + bI[i]) * 4u;
#pragma unroll
        for (int peer = 0; peer < KS; peer++)
            pr[i][peer] = ld_dsmem_f32(mapa_cluster(off, (uint32_t)peer));
    }

    CLUSTER_ARRIVE();  // barrier #2 arrive: done reading peer SMEM

    // epilogue math + global stores overlap the second barrier window
#pragma unroll
    for (int i = 0; i < 2; i++) {
        float sum = pv[i];
#pragma unroll
        for (int peer = 0; peer < KS; peer++) sum += pr[i][peer];  // fixed order: deterministic
        const float m  = (lenv[i] > t) ? 0.5f : 0.0f;              // mask * lr (lr = 1-lr = 0.5)
        const float xn = m * (xo[i] + tanh_acc(sum));
        xdst[(size_t)rI[i] * Bn + bI[i]] = xn;
        out[((size_t)bI[i] * Tn + t) * Rn + rI[i]] = xn;
    }

    CLUSTER_WAIT();    // barrier #2 wait: safe to exit (no peer still reads my SMEM)
}

// ---------------------------------------------------------------------------
// launch: init + proj + 256 clustered step kernels — all graph-capturable
// ---------------------------------------------------------------------------
extern "C" void kernel_launch(void* const* d_in, const int* in_sizes, int n_in,
                              void* d_out, int out_size) {
    const float* inp     = (const float*)d_in[0];  // [T,B,D]
    const int*   lengths = (const int*)d_in[1];    // [B]
    const float* win     = (const float*)d_in[2];  // [R,D]
    const float* wres    = (const float*)d_in[3];  // [R,R]
    const float* bias    = (const float*)d_in[4];  // [R]
    const float* x0in    = (const float*)d_in[5];  // [R]
    float* out = (float*)d_out;                    // [B,T,R]

    init_x_kernel<<<(Rn * Bn + 255) / 256, 256>>>(x0in);
    proj_kernel<<<dim3(Rn / 64, Tn), 128>>>(inp, win, bias);
    for (int t = 0; t < Tn; t++) {
        step_cluster_kernel<<<dim3(KS, 64), 128>>>(wres, lengths, out, t);
    }
}